// round 1
// baseline (speedup 1.0000x reference)
#include <cuda_runtime.h>
#include <cuda_bf16.h>
#include <math.h>

// Problem constants (from reference)
#define NN 50000
#define EE 1600000
#define IND 256
#define OUTD 64
#define NH 4

// ---------------- scratch (static device arrays; no allocation) -------------
__device__ float  g_x[NN * OUTD];          // 12.8 MB  x = h@W
__device__ float4 g_el[NN];                // el per node (4 heads)
__device__ float4 g_er[NN];                // er per node
__device__ int    g_deg[NN];
__device__ int    g_off[NN + 1];
__device__ int    g_cur[NN];
__device__ int    g_dst_s[EE];             // CSR-sorted dst
__device__ float4 g_e_s[EE];               // CSR-sorted exp(leaky(e)) per head

// ---------------- K1: x = h @ W  (M=N nodes, K=256, N=64) -------------------
// 128x64 tile per block, 256 threads, 8x4 microtile per thread.
__global__ void k_gemm(const float* __restrict__ h, const float* __restrict__ W, int N)
{
    __shared__ float  As[128 * 36];     // padded stride 36
    __shared__ float4 Bs[32 * 16];      // 32 k x 64 n as float4

    const int tid = threadIdx.x;
    const int m0  = blockIdx.x * 128;
    const int tx  = tid & 15;           // 16 col groups (4 cols each)
    const int ty  = tid >> 4;           // 16 row groups (8 rows each)

    float acc[8][4];
#pragma unroll
    for (int i = 0; i < 8; i++)
#pragma unroll
        for (int j = 0; j < 4; j++) acc[i][j] = 0.f;

    for (int k0 = 0; k0 < IND; k0 += 32) {
        // load A tile: 128 rows x 32 k = 1024 float4
#pragma unroll
        for (int l = 0; l < 4; l++) {
            int f   = tid + 256 * l;
            int row = f >> 3;
            int kq  = f & 7;
            int gm  = m0 + row;
            float4 v = make_float4(0.f, 0.f, 0.f, 0.f);
            if (gm < N) v = *(const float4*)(h + (size_t)gm * IND + k0 + kq * 4);
            *(float4*)(As + row * 36 + kq * 4) = v;
        }
        // load B tile: 32 k x 64 n = 512 float4
#pragma unroll
        for (int l = 0; l < 2; l++) {
            int f  = tid + 256 * l;
            int kk = f >> 4;
            int nq = f & 15;
            Bs[kk * 16 + nq] = *(const float4*)(W + (size_t)(k0 + kk) * OUTD + nq * 4);
        }
        __syncthreads();

#pragma unroll
        for (int k = 0; k < 32; k++) {
            float4 bv = Bs[k * 16 + tx];
#pragma unroll
            for (int i = 0; i < 8; i++) {
                float a = As[(ty * 8 + i) * 36 + k];
                acc[i][0] += a * bv.x;
                acc[i][1] += a * bv.y;
                acc[i][2] += a * bv.z;
                acc[i][3] += a * bv.w;
            }
        }
        __syncthreads();
    }

#pragma unroll
    for (int i = 0; i < 8; i++) {
        int gm = m0 + ty * 8 + i;
        if (gm < N) {
            float4 v = make_float4(acc[i][0], acc[i][1], acc[i][2], acc[i][3]);
            *(float4*)(g_x + (size_t)gm * OUTD + tx * 4) = v;
        }
    }
}

// ---------------- K2: el = x @ Wl^T, er = x @ Wr^T (warp per node) ----------
__global__ void k_elr(const float* __restrict__ Wl, const float* __restrict__ Wr, int N)
{
    int warp = (blockIdx.x * blockDim.x + threadIdx.x) >> 5;
    int lane = threadIdx.x & 31;
    if (warp >= N) return;

    const float* xr = g_x + (size_t)warp * OUTD;
    float x0 = xr[lane];
    float x1 = xr[lane + 32];

    float s[8];
#pragma unroll
    for (int hd = 0; hd < NH; hd++) {
        s[hd]     = x0 * __ldg(Wl + hd * OUTD + lane) + x1 * __ldg(Wl + hd * OUTD + lane + 32);
        s[4 + hd] = x0 * __ldg(Wr + hd * OUTD + lane) + x1 * __ldg(Wr + hd * OUTD + lane + 32);
    }
#pragma unroll
    for (int o = 16; o > 0; o >>= 1) {
#pragma unroll
        for (int j = 0; j < 8; j++) s[j] += __shfl_xor_sync(0xffffffffu, s[j], o);
    }
    if (lane == 0) {
        g_el[warp] = make_float4(s[0], s[1], s[2], s[3]);
        g_er[warp] = make_float4(s[4], s[5], s[6], s[7]);
    }
}

// ---------------- K0: zero degree histogram ---------------------------------
__global__ void k_zero(int N)
{
    int i = blockIdx.x * blockDim.x + threadIdx.x;
    if (i < N) g_deg[i] = 0;
}

// ---------------- K3: degree histogram --------------------------------------
__global__ void k_deg(const int* __restrict__ ei, int E)
{
    int e = blockIdx.x * blockDim.x + threadIdx.x;
    if (e < E) atomicAdd(&g_deg[ei[e]], 1);
}

// ---------------- K4: exclusive scan (single block, chunked) ----------------
__global__ void k_scan(int N)
{
    __shared__ int sm[1024];
    __shared__ int run;
    int t = threadIdx.x;
    if (t == 0) run = 0;
    __syncthreads();

    for (int base = 0; base < N; base += 1024) {
        int v = (base + t < N) ? g_deg[base + t] : 0;
        sm[t] = v;
        __syncthreads();
#pragma unroll
        for (int o = 1; o < 1024; o <<= 1) {
            int y = (t >= o) ? sm[t - o] : 0;
            __syncthreads();
            sm[t] += y;
            __syncthreads();
        }
        int excl = sm[t] - v;
        int o = run + excl;
        if (base + t < N) { g_off[base + t] = o; g_cur[base + t] = o; }
        __syncthreads();
        if (t == 0) run += sm[1023];
        __syncthreads();
    }
    if (t == 0) g_off[N] = run;
}

// ---------------- K5: scatter edges into CSR buckets + compute e ------------
__device__ __forceinline__ float lrelu_exp(float v)
{
    float t = (v >= 0.f) ? v : 0.2f * v;
    return expf(t);
}

__global__ void k_scatter(const int* __restrict__ ei, int E)
{
    int e = blockIdx.x * blockDim.x + threadIdx.x;
    if (e >= E) return;
    int s = ei[e];
    int d = ei[E + e];
    float4 el = g_el[s];
    float4 er = g_er[d];
    float4 ev;
    ev.x = lrelu_exp(el.x + er.x);
    ev.y = lrelu_exp(el.y + er.y);
    ev.z = lrelu_exp(el.z + er.z);
    ev.w = lrelu_exp(el.w + er.w);
    int pos = atomicAdd(&g_cur[s], 1);
    g_dst_s[pos] = d;
    g_e_s[pos] = ev;
}

// ---------------- K6: per-node aggregation (warp per node) ------------------
__device__ __forceinline__ float elu1(float v)
{
    return (v > 0.f) ? v : expm1f(v);
}

__global__ void k_agg(const float* __restrict__ b, float* __restrict__ out, int N)
{
    int warp = (blockIdx.x * blockDim.x + threadIdx.x) >> 5;
    int lane = threadIdx.x & 31;
    if (warp >= N) return;

    int s0 = g_off[warp];
    int s1 = g_off[warp + 1];

    float a00 = 0.f, a01 = 0.f, a10 = 0.f, a11 = 0.f;
    float a20 = 0.f, a21 = 0.f, a30 = 0.f, a31 = 0.f;
    float e0 = 0.f, e1 = 0.f, e2 = 0.f, e3 = 0.f;

    for (int i = s0; i < s1; i++) {
        int d = g_dst_s[i];                 // uniform per warp -> broadcast
        float4 ev = g_e_s[i];               // uniform per warp -> broadcast
        const float* xr = g_x + (size_t)d * OUTD;
        float x0 = xr[lane];
        float x1 = xr[lane + 32];
        a00 += ev.x * x0;  a01 += ev.x * x1;
        a10 += ev.y * x0;  a11 += ev.y * x1;
        a20 += ev.z * x0;  a21 += ev.z * x1;
        a30 += ev.w * x0;  a31 += ev.w * x1;
        e0 += ev.x; e1 += ev.y; e2 += ev.z; e3 += ev.w;
    }

    float i0 = 1.f / fmaxf(e0, 1e-12f);
    float i1 = 1.f / fmaxf(e1, 1e-12f);
    float i2 = 1.f / fmaxf(e2, 1e-12f);
    float i3 = 1.f / fmaxf(e3, 1e-12f);

    float b0 = __ldg(b + lane);
    float b1 = __ldg(b + lane + 32);

    float* o = out + (size_t)warp * (NH * OUTD);
    o[0 * OUTD + lane]      = elu1(a00 * i0 + b0);
    o[0 * OUTD + lane + 32] = elu1(a01 * i0 + b1);
    o[1 * OUTD + lane]      = elu1(a10 * i1 + b0);
    o[1 * OUTD + lane + 32] = elu1(a11 * i1 + b1);
    o[2 * OUTD + lane]      = elu1(a20 * i2 + b0);
    o[2 * OUTD + lane + 32] = elu1(a21 * i2 + b1);
    o[3 * OUTD + lane]      = elu1(a30 * i3 + b0);
    o[3 * OUTD + lane + 32] = elu1(a31 * i3 + b1);
}

// ---------------- launch -----------------------------------------------------
extern "C" void kernel_launch(void* const* d_in, const int* in_sizes, int n_in,
                              void* d_out, int out_size)
{
    const float* h  = (const float*)d_in[0];   // [N, 256]
    const float* W  = (const float*)d_in[1];   // [256, 64]
    const float* Wl = (const float*)d_in[2];   // [4, 64]
    const float* Wr = (const float*)d_in[3];   // [4, 64]
    const float* b  = (const float*)d_in[4];   // [64]
    const int*   ei = (const int*)d_in[5];     // [2, E]
    float* out = (float*)d_out;

    int N = in_sizes[0] / IND;
    int E = in_sizes[5] / 2;

    k_zero<<<(N + 255) / 256, 256>>>(N);
    k_gemm<<<(N + 127) / 128, 256>>>(h, W, N);
    k_elr<<<(N + 7) / 8, 256>>>(Wl, Wr, N);
    k_deg<<<(E + 255) / 256, 256>>>(ei, E);
    k_scan<<<1, 1024>>>(N);
    k_scatter<<<(E + 255) / 256, 256>>>(ei, E);
    k_agg<<<(N + 7) / 8, 256>>>(b, out, N);
}